// round 11
// baseline (speedup 1.0000x reference)
#include <cuda_runtime.h>
#include <cstdint>

#define TABLE_ROWS 1025
#define HIDDEN     128
#define SEQ        512
#define BATCH      2
#define MAXSEQ     512
#define R_MAX      44        // max contiguous table rows cached per table per tile
#define PROD_BLOCKS  258     // producer blocks (4 rows each, both tables)
#define ROWS_PER_PROD 4
#define TOTAL_BLOCKS 2048    // (SEQ/16)*(SEQ/16)*BATCH

// Scratch + sync state (allocation-free rule: device globals, zero-initialized).
__device__ float g_Ass[TABLE_ROWS * HIDDEN];   // pe_ss @ W[:, :128]^T + bias
__device__ float g_Aee[TABLE_ROWS * HIDDEN];   // pe_ee @ W[:, 128:]^T
__device__ unsigned int g_ready;               // producers finished
__device__ unsigned int g_exit;                // blocks exited (for self-reset)

// ---------------------------------------------------------------------------
// Helpers
// ---------------------------------------------------------------------------
__device__ __forceinline__ void cp_async16(uint32_t saddr, const void* gaddr)
{
    asm volatile("cp.async.cg.shared.global [%0], [%1], 16;"
                 :: "r"(saddr), "l"(gaddr) : "memory");
}

// Predicated LDS.128: load only if row != prev (warp-uniform condition);
// otherwise keep the previous value already in the registers.
__device__ __forceinline__ void lds_if(float4& v, uint32_t saddr, int row, int prev)
{
    asm volatile(
        "{\n\t.reg .pred p;\n\t"
        "setp.ne.s32 p, %4, %5;\n\t"
        "@p ld.shared.v4.f32 {%0, %1, %2, %3}, [%6];\n\t}"
        : "+f"(v.x), "+f"(v.y), "+f"(v.z), "+f"(v.w)
        : "r"(row), "r"(prev), "r"(saddr));
}

__device__ __forceinline__ unsigned int ld_acquire_gpu(const unsigned int* p)
{
    unsigned int v;
    asm volatile("ld.acquire.gpu.global.u32 %0, [%1];" : "=r"(v) : "l"(p));
    return v;
}

// ---------------------------------------------------------------------------
// Single fused kernel (v2).
// Phase 1 (flat < 258): projection, 4 table rows per block, both tables at
//   once (sel = tid>>7). ~2x the producer parallelism of R10 -> proj ~3 us.
// Sync: single flag; leaders poll with 1024 ns sleep (R10's 128 ns polling
//   saturated the flag line's LTS slice and stalled the whole chip).
// Phase 2: gather, EXACT R6 configuration (measured best, 43.8/43.9 us).
// Deadlock safety: __launch_bounds__(256,2) caps regs at 128 -> wave 1 is
//   at least 2*148=296 blocks >= 258 producers (smem 45KB allows 5 CTA/SM).
// Epilogue: last block resets counters so graph replays stay deterministic.
// ---------------------------------------------------------------------------
__global__ void __launch_bounds__(256, 2)
fused_kernel(const int* __restrict__ pos_s,
             const int* __restrict__ pos_e,
             const float* __restrict__ pe_ss,
             const float* __restrict__ pe_ee,
             const float* __restrict__ W,
             const float* __restrict__ bias,
             float* __restrict__ out)
{
    const int b    = blockIdx.z;
    const int i0   = blockIdx.y * 16;
    const int j0   = blockIdx.x * 16;
    const int flat = blockIdx.x + blockIdx.y * (SEQ / 16) +
                     blockIdx.z * (SEQ / 16) * (SEQ / 16);

    __shared__ float4 sA[R_MAX * 32];       // 22.5 KB (also pe staging in phase 1)
    __shared__ float4 sE[R_MAX * 32];       // 22.5 KB
    __shared__ int s_psi[16], s_pei[16], s_psj[16], s_pej[16];
    __shared__ int s_meta[4];               // loA, nA(0=fallback), loE, nE

    const int tid = threadIdx.x;

    // ---------------- Phase 1: projection (producer blocks only) ----------
    if (flat < PROD_BLOCKS) {
        const int t0  = flat * ROWS_PER_PROD;
        const int h   = tid & 127;
        const int sel = tid >> 7;           // 0 -> ss(+bias), 1 -> ee

        const float* __restrict__ pe = sel ? pe_ee : pe_ss;
        float* __restrict__ outA     = sel ? g_Aee : g_Ass;
        float* pes = reinterpret_cast<float*>(sA) + sel * (ROWS_PER_PROD * HIDDEN);

        #pragma unroll
        for (int r = 0; r < ROWS_PER_PROD; r++) {
            const int t = t0 + r;
            pes[r * HIDDEN + h] = (t < TABLE_ROWS) ? pe[(size_t)t * HIDDEN + h] : 0.0f;
        }
        __syncthreads();

        float acc[ROWS_PER_PROD];
        const float binit = sel ? 0.0f : bias[h];
        #pragma unroll
        for (int r = 0; r < ROWS_PER_PROD; r++) acc[r] = binit;

        const float4* __restrict__ W4 = reinterpret_cast<const float4*>(
            W + (size_t)h * (2 * HIDDEN) + sel * HIDDEN);

        #pragma unroll 8
        for (int kg = 0; kg < HIDDEN / 4; kg++) {
            const float4 w = W4[kg];
            #pragma unroll
            for (int r = 0; r < ROWS_PER_PROD; r++) {
                const float4 p =
                    reinterpret_cast<const float4*>(pes + r * HIDDEN)[kg]; // broadcast
                acc[r] += w.x * p.x + w.y * p.y + w.z * p.z + w.w * p.w;
            }
        }

        #pragma unroll
        for (int r = 0; r < ROWS_PER_PROD; r++) {
            const int t = t0 + r;
            if (t < TABLE_ROWS) outA[(size_t)t * HIDDEN + h] = acc[r];
        }

        __threadfence();                    // publish table rows gpu-wide
        __syncthreads();                    // all threads' fences done
        if (tid == 0) atomicAdd(&g_ready, 1u);
        __syncthreads();                    // sA safe to reuse below
    }

    // ---------------- Common: stage positions + tile metadata -------------
    if (tid < 16) {
        s_psi[tid] = pos_s[b * SEQ + i0 + tid];
        s_pei[tid] = pos_e[b * SEQ + i0 + tid];
        s_psj[tid] = pos_s[b * SEQ + j0 + tid];
        s_pej[tid] = pos_e[b * SEQ + j0 + tid];
    }
    __syncthreads();

    if (tid == 0) {
        int lo = s_psi[0]  - s_psj[15] + MAXSEQ;   // sorted: endpoints = extrema
        int n  = (s_psi[15] - s_psj[0] + MAXSEQ) - lo + 1;
        s_meta[0] = lo;
        s_meta[1] = (n <= R_MAX) ? n : 0;
        lo = s_pei[0]  - s_pej[15] + MAXSEQ;
        n  = (s_pei[15] - s_pej[0] + MAXSEQ) - lo + 1;
        s_meta[2] = lo;
        s_meta[3] = (n <= R_MAX) ? n : 0;

        // Wait for the full projected tables. 1024 ns sleep keeps the
        // aggregate poll rate far below one LTS slice's service rate.
        while (ld_acquire_gpu(&g_ready) < (unsigned)PROD_BLOCKS)
            __nanosleep(1024);
    }
    __syncthreads();

    const int loA = s_meta[0], nA = s_meta[1];
    const int loE = s_meta[2], nE = s_meta[3];

    const float4* __restrict__ gA = reinterpret_cast<const float4*>(g_Ass);
    const float4* __restrict__ gE = reinterpret_cast<const float4*>(g_Aee);

    const uint32_t sA_base = (uint32_t)__cvta_generic_to_shared(sA);
    const uint32_t sE_base = (uint32_t)__cvta_generic_to_shared(sE);

    const int warp = tid >> 5;
    const int lane = tid & 31;

    // ---------------- Phase 2: gather (EXACT R6 body) ---------------------
    if (nA && nE) {
        for (int t = tid; t < nA * 32; t += 256)
            cp_async16(sA_base + t * 16, gA + loA * 32 + t);
        for (int t = tid; t < nE * 32; t += 256)
            cp_async16(sE_base + t * 16, gE + loE * 32 + t);
        asm volatile("cp.async.commit_group;\ncp.async.wait_group 0;" ::: "memory");
        __syncthreads();

        #pragma unroll
        for (int half = 0; half < 2; half++) {
            const int ii = warp * 2 + half;
            const int baseA = s_psi[ii] + MAXSEQ - loA;   // row = baseA - psj
            const int baseE = s_pei[ii] + MAXSEQ - loE;
            float4* __restrict__ orow = reinterpret_cast<float4*>(out) +
                (((size_t)b * SEQ + (i0 + ii)) * SEQ + j0) * (HIDDEN / 4) + lane;

            int prevA = -1, prevE = -1;
            float4 a = make_float4(0.f, 0.f, 0.f, 0.f);
            float4 e = make_float4(0.f, 0.f, 0.f, 0.f);

            #pragma unroll
            for (int jj = 0; jj < 16; jj++) {
                const int rA = baseA - s_psj[jj];         // warp-uniform
                const int rE = baseE - s_pej[jj];

                lds_if(a, sA_base + (rA * 32 + lane) * 16, rA, prevA);
                lds_if(e, sE_base + (rE * 32 + lane) * 16, rE, prevE);
                prevA = rA;
                prevE = rE;

                float4 r;
                r.x = fmaxf(a.x + e.x, 0.0f);
                r.y = fmaxf(a.y + e.y, 0.0f);
                r.z = fmaxf(a.z + e.z, 0.0f);
                r.w = fmaxf(a.w + e.w, 0.0f);

                orow[jj * (HIDDEN / 4)] = r;
            }
        }
    } else {
        // Cold path: range too wide for SMEM — direct global gathers.
        #pragma unroll
        for (int half = 0; half < 2; half++) {
            const int ii  = warp * 2 + half;
            const int psi = s_psi[ii];
            const int pei = s_pei[ii];
            float4* __restrict__ orow = reinterpret_cast<float4*>(out) +
                (((size_t)b * SEQ + (i0 + ii)) * SEQ + j0) * (HIDDEN / 4) + lane;

            for (int jj = 0; jj < 16; jj++) {
                const int iss = psi - s_psj[jj] + MAXSEQ;
                const int iee = pei - s_pej[jj] + MAXSEQ;
                const float4 a = __ldg(gA + iss * 32 + lane);
                const float4 e = __ldg(gE + iee * 32 + lane);
                float4 r;
                r.x = fmaxf(a.x + e.x, 0.0f);
                r.y = fmaxf(a.y + e.y, 0.0f);
                r.z = fmaxf(a.z + e.z, 0.0f);
                r.w = fmaxf(a.w + e.w, 0.0f);
                orow[jj * (HIDDEN / 4)] = r;
            }
        }
    }

    // ---------------- Epilogue: self-resetting counters --------------------
    __syncthreads();
    if (tid == 0) {
        const unsigned int n = atomicAdd(&g_exit, 1u);
        if (n == (unsigned)(TOTAL_BLOCKS - 1)) {
            g_ready = 0u;           // all blocks are past the spin; safe to reset
            g_exit  = 0u;
            __threadfence();
        }
    }
}

// ---------------------------------------------------------------------------
// Inputs (metadata order): 0 pos_s [B,S] i32, 1 pos_e [B,S] i32,
// 2 pe_ss [1025,128] f32, 3 pe_se (unused), 4 pe_es (unused),
// 5 pe_ee [1025,128] f32, 6 W [128,256] f32, 7 b [128] f32.
// Output: [B,S,S,H] f32.
// ---------------------------------------------------------------------------
extern "C" void kernel_launch(void* const* d_in, const int* in_sizes, int n_in,
                              void* d_out, int out_size)
{
    const int*   pos_s = (const int*)d_in[0];
    const int*   pos_e = (const int*)d_in[1];
    const float* pe_ss = (const float*)d_in[2];
    const float* pe_ee = (const float*)d_in[5];
    const float* W     = (const float*)d_in[6];
    const float* bias  = (const float*)d_in[7];
    float*       out   = (float*)d_out;

    dim3 grid(SEQ / 16, SEQ / 16, BATCH);   // 2048 blocks
    fused_kernel<<<grid, 256>>>(pos_s, pos_e, pe_ss, pe_ee, W, bias, out);
}

// round 12
// speedup vs baseline: 1.0965x; 1.0965x over previous
#include <cuda_runtime.h>
#include <cstdint>

#define TABLE_ROWS 1025
#define HIDDEN     128
#define SEQ        512
#define BATCH      2
#define MAXSEQ     512
#define R_MAX      44      // max contiguous table rows cached per table per tile

// Scratch for the projected tables (allocation-free rule: device globals).
__device__ float g_Ass[TABLE_ROWS * HIDDEN];   // pe_ss @ W[:, :128]^T + bias
__device__ float g_Aee[TABLE_ROWS * HIDDEN];   // pe_ee @ W[:, 128:]^T

// ---------------------------------------------------------------------------
// Kernel 1 v4: R1 shape (grid (129,2), block 128, 8 rows/block) but W is
// staged through SMEM in 32-column transposed chunks:
//   - global reads of W are fully coalesced (warp reads 128 contiguous bytes)
//   - the FFMA loop reads W via conflict-free LDS (pad +1)
// This removes the nL=32 pathology (lanes 1 KB apart) that made every
// previous k1 variant latency-bound on scattered W wavefronts.
// ---------------------------------------------------------------------------
__global__ void __launch_bounds__(128)
project_tables_kernel(const float* __restrict__ pe_ss,
                      const float* __restrict__ pe_ee,
                      const float* __restrict__ W,
                      const float* __restrict__ bias)
{
    const int sel = blockIdx.y;            // 0 -> ss(+bias), 1 -> ee
    const int t0  = blockIdx.x * 8;
    const int h   = threadIdx.x;           // 0..127 output column

    const float* __restrict__ pe = sel ? pe_ee : pe_ss;
    float* __restrict__ outA     = sel ? g_Aee : g_Ass;

    __shared__ float pe_sm[8][HIDDEN];     // 4 KB
    __shared__ float wT[32][129];          // 16.5 KB: one transposed k-chunk

    #pragma unroll
    for (int r = 0; r < 8; r++) {
        const int t = t0 + r;
        pe_sm[r][h] = (t < TABLE_ROWS) ? pe[(size_t)t * HIDDEN + h] : 0.0f;
    }

    float acc[8];
    const float binit = sel ? 0.0f : bias[h];
    #pragma unroll
    for (int r = 0; r < 8; r++) acc[r] = binit;

    const float* __restrict__ Wsel = W + sel * HIDDEN;

    #pragma unroll 1
    for (int kc = 0; kc < 4; kc++) {       // four 32-wide k chunks
        __syncthreads();                    // wT reuse (covers pe_sm on iter 0)
        // Load W[:, kc*32 .. +32) coalesced; store transposed (pad-free banks).
        #pragma unroll
        for (int i = 0; i < 32; i++) {
            const int l = i * 128 + h;      // 0..4095
            const int r = l >> 5;           // W row 0..127
            const int c = l & 31;           // k within chunk
            wT[c][r] = Wsel[(size_t)r * (2 * HIDDEN) + kc * 32 + c];
        }
        __syncthreads();

        #pragma unroll
        for (int kg = 0; kg < 8; kg++) {
            const float w0 = wT[kg * 4 + 0][h];   // lanes consecutive: no conflict
            const float w1 = wT[kg * 4 + 1][h];
            const float w2 = wT[kg * 4 + 2][h];
            const float w3 = wT[kg * 4 + 3][h];
            #pragma unroll
            for (int r = 0; r < 8; r++) {
                const float4 p =
                    reinterpret_cast<const float4*>(pe_sm[r])[kc * 8 + kg]; // broadcast
                acc[r] += p.x * w0 + p.y * w1 + p.z * w2 + p.w * w3;
            }
        }
    }

    #pragma unroll
    for (int r = 0; r < 8; r++) {
        const int t = t0 + r;
        if (t < TABLE_ROWS) outA[(size_t)t * HIDDEN + h] = acc[r];
    }
}

// ---------------------------------------------------------------------------
// Helpers for kernel 2
// ---------------------------------------------------------------------------
__device__ __forceinline__ void cp_async16(uint32_t saddr, const void* gaddr)
{
    asm volatile("cp.async.cg.shared.global [%0], [%1], 16;"
                 :: "r"(saddr), "l"(gaddr) : "memory");
}

// Predicated LDS.128: load only if row != prev (warp-uniform condition);
// otherwise keep the previous value already in the registers.
__device__ __forceinline__ void lds_if(float4& v, uint32_t saddr, int row, int prev)
{
    asm volatile(
        "{\n\t.reg .pred p;\n\t"
        "setp.ne.s32 p, %4, %5;\n\t"
        "@p ld.shared.v4.f32 {%0, %1, %2, %3}, [%6];\n\t}"
        : "+f"(v.x), "+f"(v.y), "+f"(v.z), "+f"(v.w)
        : "r"(row), "r"(prev), "r"(saddr));
}

// ---------------------------------------------------------------------------
// Kernel 2 — EXACT R6 body (measured best 43.8/43.9 us), plus PDL:
// launched with ProgrammaticStreamSerialization so its prologue (positions,
// metadata) overlaps kernel 1; cudaGridDependencySynchronize() (hardware
// event, no polling) gates only the table reads.
// ---------------------------------------------------------------------------
__global__ void __launch_bounds__(256)
fuse_gather_tiled(const int* __restrict__ pos_s,
                  const int* __restrict__ pos_e,
                  float* __restrict__ out)
{
    const int b  = blockIdx.z;
    const int i0 = blockIdx.y * 16;
    const int j0 = blockIdx.x * 16;

    __shared__ float4 sA[R_MAX * 32];       // 22.5 KB
    __shared__ float4 sE[R_MAX * 32];       // 22.5 KB
    __shared__ int s_psi[16], s_pei[16], s_psj[16], s_pej[16];
    __shared__ int s_meta[4];               // loA, nA(0=fallback), loE, nE

    const int tid = threadIdx.x;

    // Prologue — independent of kernel 1, overlaps it under PDL.
    if (tid < 16) {
        s_psi[tid] = pos_s[b * SEQ + i0 + tid];
        s_pei[tid] = pos_e[b * SEQ + i0 + tid];
        s_psj[tid] = pos_s[b * SEQ + j0 + tid];
        s_pej[tid] = pos_e[b * SEQ + j0 + tid];
    }
    __syncthreads();

    if (tid == 0) {
        int lo = s_psi[0]  - s_psj[15] + MAXSEQ;   // sorted: endpoints = extrema
        int n  = (s_psi[15] - s_psj[0] + MAXSEQ) - lo + 1;
        s_meta[0] = lo;
        s_meta[1] = (n <= R_MAX) ? n : 0;
        lo = s_pei[0]  - s_pej[15] + MAXSEQ;
        n  = (s_pei[15] - s_pej[0] + MAXSEQ) - lo + 1;
        s_meta[2] = lo;
        s_meta[3] = (n <= R_MAX) ? n : 0;
    }
    __syncthreads();

    // Hardware wait for kernel 1 completion (tables published).
    cudaGridDependencySynchronize();

    const int loA = s_meta[0], nA = s_meta[1];
    const int loE = s_meta[2], nE = s_meta[3];

    const float4* __restrict__ gA = reinterpret_cast<const float4*>(g_Ass);
    const float4* __restrict__ gE = reinterpret_cast<const float4*>(g_Aee);

    const uint32_t sA_base = (uint32_t)__cvta_generic_to_shared(sA);
    const uint32_t sE_base = (uint32_t)__cvta_generic_to_shared(sE);

    const int warp = tid >> 5;
    const int lane = tid & 31;

    if (nA && nE) {
        for (int t = tid; t < nA * 32; t += 256)
            cp_async16(sA_base + t * 16, gA + loA * 32 + t);
        for (int t = tid; t < nE * 32; t += 256)
            cp_async16(sE_base + t * 16, gE + loE * 32 + t);
        asm volatile("cp.async.commit_group;\ncp.async.wait_group 0;" ::: "memory");
        __syncthreads();

        #pragma unroll
        for (int half = 0; half < 2; half++) {
            const int ii = warp * 2 + half;
            const int baseA = s_psi[ii] + MAXSEQ - loA;   // row = baseA - psj
            const int baseE = s_pei[ii] + MAXSEQ - loE;
            float4* __restrict__ orow = reinterpret_cast<float4*>(out) +
                (((size_t)b * SEQ + (i0 + ii)) * SEQ + j0) * (HIDDEN / 4) + lane;

            int prevA = -1, prevE = -1;
            float4 a = make_float4(0.f, 0.f, 0.f, 0.f);
            float4 e = make_float4(0.f, 0.f, 0.f, 0.f);

            #pragma unroll
            for (int jj = 0; jj < 16; jj++) {
                const int rA = baseA - s_psj[jj];         // warp-uniform
                const int rE = baseE - s_pej[jj];

                lds_if(a, sA_base + (rA * 32 + lane) * 16, rA, prevA);
                lds_if(e, sE_base + (rE * 32 + lane) * 16, rE, prevE);
                prevA = rA;
                prevE = rE;

                float4 r;
                r.x = fmaxf(a.x + e.x, 0.0f);
                r.y = fmaxf(a.y + e.y, 0.0f);
                r.z = fmaxf(a.z + e.z, 0.0f);
                r.w = fmaxf(a.w + e.w, 0.0f);

                orow[jj * (HIDDEN / 4)] = r;
            }
        }
    } else {
        // Cold path: range too wide for SMEM — direct global gathers.
        #pragma unroll
        for (int half = 0; half < 2; half++) {
            const int ii  = warp * 2 + half;
            const int psi = s_psi[ii];
            const int pei = s_pei[ii];
            float4* __restrict__ orow = reinterpret_cast<float4*>(out) +
                (((size_t)b * SEQ + (i0 + ii)) * SEQ + j0) * (HIDDEN / 4) + lane;

            for (int jj = 0; jj < 16; jj++) {
                const int iss = psi - s_psj[jj] + MAXSEQ;
                const int iee = pei - s_pej[jj] + MAXSEQ;
                const float4 a = __ldg(gA + iss * 32 + lane);
                const float4 e = __ldg(gE + iee * 32 + lane);
                float4 r;
                r.x = fmaxf(a.x + e.x, 0.0f);
                r.y = fmaxf(a.y + e.y, 0.0f);
                r.z = fmaxf(a.z + e.z, 0.0f);
                r.w = fmaxf(a.w + e.w, 0.0f);
                orow[jj * (HIDDEN / 4)] = r;
            }
        }
    }
}

// ---------------------------------------------------------------------------
// Inputs (metadata order): 0 pos_s [B,S] i32, 1 pos_e [B,S] i32,
// 2 pe_ss [1025,128] f32, 3 pe_se (unused), 4 pe_es (unused),
// 5 pe_ee [1025,128] f32, 6 W [128,256] f32, 7 b [128] f32.
// Output: [B,S,S,H] f32.
// ---------------------------------------------------------------------------
extern "C" void kernel_launch(void* const* d_in, const int* in_sizes, int n_in,
                              void* d_out, int out_size)
{
    const int*   pos_s = (const int*)d_in[0];
    const int*   pos_e = (const int*)d_in[1];
    const float* pe_ss = (const float*)d_in[2];
    const float* pe_ee = (const float*)d_in[5];
    const float* W     = (const float*)d_in[6];
    const float* bias  = (const float*)d_in[7];
    float*       out   = (float*)d_out;

    dim3 grid1((TABLE_ROWS + 7) / 8, 2);
    project_tables_kernel<<<grid1, 128>>>(pe_ss, pe_ee, W, bias);

    // Gather with programmatic dependent launch: prologue overlaps kernel 1.
    cudaLaunchConfig_t cfg = {};
    cfg.gridDim  = dim3(SEQ / 16, SEQ / 16, BATCH);
    cfg.blockDim = dim3(256, 1, 1);
    cfg.stream   = 0;                        // legacy default (same as <<<>>>)
    cudaLaunchAttribute attrs[1];
    attrs[0].id = cudaLaunchAttributeProgrammaticStreamSerialization;
    attrs[0].val.programmaticStreamSerializationAllowed = 1;
    cfg.attrs    = attrs;
    cfg.numAttrs = 1;
    cudaLaunchKernelEx(&cfg, fuse_gather_tiled, pos_s, pos_e, (float*)d_out);
}

// round 13
// speedup vs baseline: 1.1441x; 1.0435x over previous
#include <cuda_runtime.h>
#include <cstdint>

#define TABLE_ROWS 1025
#define HIDDEN     128
#define SEQ        512
#define BATCH      2
#define MAXSEQ     512
#define R_MAX      44      // max contiguous table rows cached per table per tile

// Scratch for the projected tables (allocation-free rule: device globals).
__device__ float g_Ass[TABLE_ROWS * HIDDEN];   // pe_ss @ W[:, :128]^T + bias
__device__ float g_Aee[TABLE_ROWS * HIDDEN];   // pe_ee @ W[:, 128:]^T

// ---------------------------------------------------------------------------
// Kernel 1 — EXACT R1 config (measured best of all k1 variants across
// R1/R3/R4/R8/R9/R12 experiments): grid (129,2), block 128, 8 rows/block.
// ---------------------------------------------------------------------------
__global__ void __launch_bounds__(128)
project_tables_kernel(const float* __restrict__ pe_ss,
                      const float* __restrict__ pe_ee,
                      const float* __restrict__ W,
                      const float* __restrict__ bias)
{
    const int sel = blockIdx.y;            // 0 -> ss(+bias), 1 -> ee
    const int t0  = blockIdx.x * 8;
    const int h   = threadIdx.x;           // 0..127

    const float* __restrict__ pe = sel ? pe_ee : pe_ss;
    float* __restrict__ outA     = sel ? g_Aee : g_Ass;

    __shared__ float pe_sm[8][HIDDEN];

    #pragma unroll
    for (int r = 0; r < 8; r++) {
        int t = t0 + r;
        pe_sm[r][h] = (t < TABLE_ROWS) ? pe[(size_t)t * HIDDEN + h] : 0.0f;
    }
    __syncthreads();

    float acc[8];
    const float binit = sel ? 0.0f : bias[h];
    #pragma unroll
    for (int r = 0; r < 8; r++) acc[r] = binit;

    const float4* __restrict__ W4 =
        reinterpret_cast<const float4*>(W + (size_t)h * (2 * HIDDEN) + sel * HIDDEN);

    #pragma unroll 8
    for (int kg = 0; kg < HIDDEN / 4; kg++) {
        const float4 w = W4[kg];
        #pragma unroll
        for (int r = 0; r < 8; r++) {
            const float4 p = reinterpret_cast<const float4*>(pe_sm[r])[kg]; // broadcast
            acc[r] += w.x * p.x + w.y * p.y + w.z * p.z + w.w * p.w;
        }
    }

    #pragma unroll
    for (int r = 0; r < 8; r++) {
        int t = t0 + r;
        if (t < TABLE_ROWS) outA[(size_t)t * HIDDEN + h] = acc[r];
    }
}

// ---------------------------------------------------------------------------
// Helpers for kernel 2
// ---------------------------------------------------------------------------
__device__ __forceinline__ void cp_async16(uint32_t saddr, const void* gaddr)
{
    asm volatile("cp.async.cg.shared.global [%0], [%1], 16;"
                 :: "r"(saddr), "l"(gaddr) : "memory");
}

// Predicated LDS.128: load only if row != prev (warp-uniform condition);
// otherwise keep the previous value already in the registers.
__device__ __forceinline__ void lds_if(float4& v, uint32_t saddr, int row, int prev)
{
    asm volatile(
        "{\n\t.reg .pred p;\n\t"
        "setp.ne.s32 p, %4, %5;\n\t"
        "@p ld.shared.v4.f32 {%0, %1, %2, %3}, [%6];\n\t}"
        : "+f"(v.x), "+f"(v.y), "+f"(v.z), "+f"(v.w)
        : "r"(row), "r"(prev), "r"(saddr));
}

// ---------------------------------------------------------------------------
// Kernel 2 — EXACT R6 body (measured best, 43.8/43.9/44.1 us) with PDL:
// prologue (positions, metadata) overlaps kernel 1 under
// ProgrammaticStreamSerialization; cudaGridDependencySynchronize() gates
// only the table reads (hardware event, no polling).
// ---------------------------------------------------------------------------
__global__ void __launch_bounds__(256)
fuse_gather_tiled(const int* __restrict__ pos_s,
                  const int* __restrict__ pos_e,
                  float* __restrict__ out)
{
    const int b  = blockIdx.z;
    const int i0 = blockIdx.y * 16;
    const int j0 = blockIdx.x * 16;

    __shared__ float4 sA[R_MAX * 32];       // 22.5 KB
    __shared__ float4 sE[R_MAX * 32];       // 22.5 KB
    __shared__ int s_psi[16], s_pei[16], s_psj[16], s_pej[16];
    __shared__ int s_meta[4];               // loA, nA(0=fallback), loE, nE

    const int tid = threadIdx.x;

    // Prologue — independent of kernel 1, overlaps it under PDL.
    if (tid < 16) {
        s_psi[tid] = pos_s[b * SEQ + i0 + tid];
        s_pei[tid] = pos_e[b * SEQ + i0 + tid];
        s_psj[tid] = pos_s[b * SEQ + j0 + tid];
        s_pej[tid] = pos_e[b * SEQ + j0 + tid];
    }
    __syncthreads();

    if (tid == 0) {
        int lo = s_psi[0]  - s_psj[15] + MAXSEQ;   // sorted: endpoints = extrema
        int n  = (s_psi[15] - s_psj[0] + MAXSEQ) - lo + 1;
        s_meta[0] = lo;
        s_meta[1] = (n <= R_MAX) ? n : 0;
        lo = s_pei[0]  - s_pej[15] + MAXSEQ;
        n  = (s_pei[15] - s_pej[0] + MAXSEQ) - lo + 1;
        s_meta[2] = lo;
        s_meta[3] = (n <= R_MAX) ? n : 0;
    }
    __syncthreads();

    // Hardware wait for kernel 1 completion (tables published).
    cudaGridDependencySynchronize();

    const int loA = s_meta[0], nA = s_meta[1];
    const int loE = s_meta[2], nE = s_meta[3];

    const float4* __restrict__ gA = reinterpret_cast<const float4*>(g_Ass);
    const float4* __restrict__ gE = reinterpret_cast<const float4*>(g_Aee);

    const uint32_t sA_base = (uint32_t)__cvta_generic_to_shared(sA);
    const uint32_t sE_base = (uint32_t)__cvta_generic_to_shared(sE);

    const int warp = tid >> 5;
    const int lane = tid & 31;

    if (nA && nE) {
        for (int t = tid; t < nA * 32; t += 256)
            cp_async16(sA_base + t * 16, gA + loA * 32 + t);
        for (int t = tid; t < nE * 32; t += 256)
            cp_async16(sE_base + t * 16, gE + loE * 32 + t);
        asm volatile("cp.async.commit_group;\ncp.async.wait_group 0;" ::: "memory");
        __syncthreads();

        #pragma unroll
        for (int half = 0; half < 2; half++) {
            const int ii = warp * 2 + half;
            const int baseA = s_psi[ii] + MAXSEQ - loA;   // row = baseA - psj
            const int baseE = s_pei[ii] + MAXSEQ - loE;
            float4* __restrict__ orow = reinterpret_cast<float4*>(out) +
                (((size_t)b * SEQ + (i0 + ii)) * SEQ + j0) * (HIDDEN / 4) + lane;

            int prevA = -1, prevE = -1;
            float4 a = make_float4(0.f, 0.f, 0.f, 0.f);
            float4 e = make_float4(0.f, 0.f, 0.f, 0.f);

            #pragma unroll
            for (int jj = 0; jj < 16; jj++) {
                const int rA = baseA - s_psj[jj];         // warp-uniform
                const int rE = baseE - s_pej[jj];

                lds_if(a, sA_base + (rA * 32 + lane) * 16, rA, prevA);
                lds_if(e, sE_base + (rE * 32 + lane) * 16, rE, prevE);
                prevA = rA;
                prevE = rE;

                float4 r;
                r.x = fmaxf(a.x + e.x, 0.0f);
                r.y = fmaxf(a.y + e.y, 0.0f);
                r.z = fmaxf(a.z + e.z, 0.0f);
                r.w = fmaxf(a.w + e.w, 0.0f);

                orow[jj * (HIDDEN / 4)] = r;
            }
        }
    } else {
        // Cold path: range too wide for SMEM — direct global gathers.
        #pragma unroll
        for (int half = 0; half < 2; half++) {
            const int ii  = warp * 2 + half;
            const int psi = s_psi[ii];
            const int pei = s_pei[ii];
            float4* __restrict__ orow = reinterpret_cast<float4*>(out) +
                (((size_t)b * SEQ + (i0 + ii)) * SEQ + j0) * (HIDDEN / 4) + lane;

            for (int jj = 0; jj < 16; jj++) {
                const int iss = psi - s_psj[jj] + MAXSEQ;
                const int iee = pei - s_pej[jj] + MAXSEQ;
                const float4 a = __ldg(gA + iss * 32 + lane);
                const float4 e = __ldg(gE + iee * 32 + lane);
                float4 r;
                r.x = fmaxf(a.x + e.x, 0.0f);
                r.y = fmaxf(a.y + e.y, 0.0f);
                r.z = fmaxf(a.z + e.z, 0.0f);
                r.w = fmaxf(a.w + e.w, 0.0f);
                orow[jj * (HIDDEN / 4)] = r;
            }
        }
    }
}

// ---------------------------------------------------------------------------
// Inputs (metadata order): 0 pos_s [B,S] i32, 1 pos_e [B,S] i32,
// 2 pe_ss [1025,128] f32, 3 pe_se (unused), 4 pe_es (unused),
// 5 pe_ee [1025,128] f32, 6 W [128,256] f32, 7 b [128] f32.
// Output: [B,S,S,H] f32.
// ---------------------------------------------------------------------------
extern "C" void kernel_launch(void* const* d_in, const int* in_sizes, int n_in,
                              void* d_out, int out_size)
{
    const int*   pos_s = (const int*)d_in[0];
    const int*   pos_e = (const int*)d_in[1];
    const float* pe_ss = (const float*)d_in[2];
    const float* pe_ee = (const float*)d_in[5];
    const float* W     = (const float*)d_in[6];
    const float* bias  = (const float*)d_in[7];
    float*       out   = (float*)d_out;

    dim3 grid1((TABLE_ROWS + 7) / 8, 2);
    project_tables_kernel<<<grid1, 128>>>(pe_ss, pe_ee, W, bias);

    // Gather with programmatic dependent launch: prologue overlaps kernel 1.
    cudaLaunchConfig_t cfg = {};
    cfg.gridDim  = dim3(SEQ / 16, SEQ / 16, BATCH);
    cfg.blockDim = dim3(256, 1, 1);
    cfg.stream   = 0;                        // legacy default (same as <<<>>>)
    cudaLaunchAttribute attrs[1];
    attrs[0].id = cudaLaunchAttributeProgrammaticStreamSerialization;
    attrs[0].val.programmaticStreamSerializationAllowed = 1;
    cfg.attrs    = attrs;
    cfg.numAttrs = 1;
    cudaLaunchKernelEx(&cfg, fuse_gather_tiled, pos_s, pos_e, (float*)d_out);
}